// round 15
// baseline (speedup 1.0000x reference)
#include <cuda_runtime.h>
#include <cuda_fp16.h>
#include <cstdint>

#define T_SEQ 4096
#define C_DIM 1024
#define QKV_DIM 3072
#define NHEAD 16
#define DHEAD 64

// ---------------------------------------------------------------------------
// Static device scratch (no allocations allowed)
// ---------------------------------------------------------------------------
__device__ __half g_xh[T_SEQ * C_DIM];            // x fp16
__device__ __half g_Wh[QKV_DIM * C_DIM];          // [Wq;Wk;Wv] fp16
__device__ __half g_Wph[C_DIM * C_DIM];           // Wp fp16
__device__ float  g_bqkv[QKV_DIM];
__device__ __half g_qkvh[T_SEQ * QKV_DIM];        // q | k | v, fp16 (q pre-scaled)
__device__ __half g_yh[T_SEQ * C_DIM];            // y fp16

// q pre-scale: (1/sqrt(64)) * log2(e), so softmax uses ex2 directly
#define QSCALE 0.18033688011112042f

// ---------------------------------------------------------------------------
// PTX helpers (arch-agnostic; no tcgen05 — harness PTX target rejects it)
// ---------------------------------------------------------------------------
__device__ __forceinline__ uint32_t smem_u32(const void* p) {
    uint32_t a;
    asm("{ .reg .u64 t; cvta.to.shared.u64 t, %1; cvt.u32.u64 %0, t; }"
        : "=r"(a) : "l"(p));
    return a;
}
__device__ __forceinline__ void cp16(uint32_t dst, const void* src) {
    asm volatile("cp.async.cg.shared.global [%0], [%1], 16;" :: "r"(dst), "l"(src));
}
__device__ __forceinline__ void cp_commit() {
    asm volatile("cp.async.commit_group;" ::: "memory");
}
__device__ __forceinline__ void cp_wait0() {
    asm volatile("cp.async.wait_group 0;" ::: "memory");
}
__device__ __forceinline__ void cp_wait1() {
    asm volatile("cp.async.wait_group 1;" ::: "memory");
}
__device__ __forceinline__ void cp_wait2() {
    asm volatile("cp.async.wait_group 2;" ::: "memory");
}
__device__ __forceinline__ void ldsm4(uint32_t* r, uint32_t addr) {
    asm volatile("ldmatrix.sync.aligned.m8n8.x4.shared.b16 {%0,%1,%2,%3}, [%4];"
                 : "=r"(r[0]), "=r"(r[1]), "=r"(r[2]), "=r"(r[3]) : "r"(addr));
}
__device__ __forceinline__ void ldsm4t(uint32_t* r, uint32_t addr) {
    asm volatile("ldmatrix.sync.aligned.m8n8.x4.trans.shared.b16 {%0,%1,%2,%3}, [%4];"
                 : "=r"(r[0]), "=r"(r[1]), "=r"(r[2]), "=r"(r[3]) : "r"(addr));
}
// fp16 MMA, fp32 accumulate (rt ~16/SMSP measured)
__device__ __forceinline__ void mma16816(float* c, const uint32_t* a, const uint32_t* b) {
    asm volatile(
        "mma.sync.aligned.m16n8k16.row.col.f32.f16.f16.f32 "
        "{%0,%1,%2,%3}, {%4,%5,%6,%7}, {%8,%9}, {%0,%1,%2,%3};"
        : "+f"(c[0]), "+f"(c[1]), "+f"(c[2]), "+f"(c[3])
        : "r"(a[0]), "r"(a[1]), "r"(a[2]), "r"(a[3]), "r"(b[0]), "r"(b[1]));
}
__device__ __forceinline__ uint32_t packhf(float a, float b) {
    __half2 t = __floats2half2_rn(a, b);
    return *(uint32_t*)&t;
}
__device__ __forceinline__ float ex2(float x) {
    float r;
    asm("ex2.approx.ftz.f32 %0, %1;" : "=f"(r) : "f"(x));
    return r;
}

// ---- mbarrier (sm_80/90 PTX, legal at compute_103) ------------------------
__device__ __forceinline__ void mbar_init(uint32_t a, uint32_t cnt) {
    asm volatile("mbarrier.init.shared.b64 [%0], %1;" :: "r"(a), "r"(cnt) : "memory");
}
__device__ __forceinline__ void mbar_arrive(uint32_t a) {
    asm volatile("{\n\t.reg .b64 t;\n\tmbarrier.arrive.shared.b64 t, [%0];\n\t}"
                 :: "r"(a) : "memory");
}
__device__ __forceinline__ void cp_arrive_noinc(uint32_t a) {
    asm volatile("cp.async.mbarrier.arrive.noinc.shared.b64 [%0];" :: "r"(a) : "memory");
}
__device__ __forceinline__ void mbar_wait(uint32_t a, uint32_t ph) {
    asm volatile(
        "{\n\t.reg .pred P;\n\t"
        "WL%=:\n\t"
        "mbarrier.try_wait.parity.shared.b64 P, [%0], %1;\n\t"
        "@!P bra WL%=;\n\t}"
        :: "r"(a), "r"(ph) : "memory");
}

#define SW128(o) ((o) ^ (((o) >> 3) & 0x70))

// ---------------------------------------------------------------------------
// Elementwise converts
// ---------------------------------------------------------------------------
__global__ void conv_x(const float4* __restrict__ src, __half2* __restrict__ h, int n4)
{
    int i = blockIdx.x * blockDim.x + threadIdx.x;
    if (i >= n4) return;
    float4 v = src[i];
    h[i * 2]     = __floats2half2_rn(v.x, v.y);
    h[i * 2 + 1] = __floats2half2_rn(v.z, v.w);
}

__global__ void conv_w4(const float4* __restrict__ Wq, const float4* __restrict__ Wk,
                        const float4* __restrict__ Wv, const float4* __restrict__ Wp,
                        __half2* __restrict__ Wh, __half2* __restrict__ Wph)
{
    int w = blockIdx.x >> 10;
    int i = (blockIdx.x & 1023) * blockDim.x + threadIdx.x;
    const float4* src = (w == 0) ? Wq : (w == 1) ? Wk : (w == 2) ? Wv : Wp;
    __half2* dst = (w == 3) ? Wph : Wh + (size_t)w * 524288;
    float4 v = src[i];
    dst[i * 2]     = __floats2half2_rn(v.x, v.y);
    dst[i * 2 + 1] = __floats2half2_rn(v.z, v.w);
}

__global__ void concat_bias(const float* __restrict__ bq, const float* __restrict__ bk,
                            const float* __restrict__ bv, float* __restrict__ dst)
{
    int i = blockIdx.x * blockDim.x + threadIdx.x;
    if (i < 1024)      dst[i] = bq[i];
    else if (i < 2048) dst[i] = bk[i - 1024];
    else               dst[i] = bv[i - 2048];
}

// ---------------------------------------------------------------------------
// fp16 single-product GEMM (NT): C = A @ B^T + bias, fp32 acc.
// CTA 128x64, BK=64, 8 warps 4m x 2n, frag double-buffering.
// 3-stage cp.async (72KB smem, still 2 CTAs/SM), ONE __syncthreads per chunk:
// wait(stage c) -> sync -> issue load(c+2) -> compute. Load is 2 chunks deep
// when consumed, covering L2 latency across the barrier.
// mode 0: fp32 C.   mode 1: fp16 Ch, QSCALE applied to cols < C_DIM.
// ---------------------------------------------------------------------------
#define GEMM_STAGE 24576
#define GEMM_SMEM  (3 * GEMM_STAGE)

__global__ __launch_bounds__(256, 2)
void gemm_f16(const __half* __restrict__ A, const __half* __restrict__ B,
              const float* __restrict__ bias, float* __restrict__ C,
              __half* __restrict__ Ch, int N, int K, int mode)
{
    extern __shared__ char smem[];
    const int tid  = threadIdx.x;
    const int warp = tid >> 5;
    const int lane = tid & 31;
    const int wm   = warp >> 1;
    const int wn   = warp & 1;
    const int m0   = blockIdx.y * 128;
    const int n0   = blockIdx.x * 64;
    const uint32_t sbase = smem_u32(smem);
    const int NC = K / 64;   // 16

    const int lrA = tid >> 1;
    const int ljA = (tid & 1) * 4;
    const int lrB = tid >> 2;
    const int ljB = (tid & 3) * 2;

    auto load_stage = [&](int c) {
        const uint32_t sb = sbase + (c % 3) * GEMM_STAGE;
        const size_t ka = (size_t)(m0 + lrA) * K + c * 64;
        const size_t kb = (size_t)(n0 + lrB) * K + c * 64;
#pragma unroll
        for (int j = ljA; j < ljA + 4; j++) {
            uint32_t sw = SW128(lrA * 128 + j * 16);
            cp16(sb + sw, A + ka + j * 8);
        }
#pragma unroll
        for (int j = ljB; j < ljB + 2; j++) {
            uint32_t sw = SW128(lrB * 128 + j * 16);
            cp16(sb + 16384 + sw, B + kb + j * 8);
        }
        cp_commit();
    };

    float acc[2][4][4];
#pragma unroll
    for (int i = 0; i < 2; i++)
#pragma unroll
        for (int j = 0; j < 4; j++)
#pragma unroll
            for (int q = 0; q < 4; q++) acc[i][j][q] = 0.f;

    const int alr = lane & 15;
    const int alk = (lane >> 4) & 1;
    const int b4r = ((lane >> 4) & 1) * 8 + (lane & 7);
    const int b4c = (lane >> 3) & 1;

    uint32_t ahb[2][2][4], bhb[2][2][4];

    load_stage(0);
    load_stage(1);

    for (int c = 0; c < NC; c++) {
        // wait for stage c: allow (issued_after_c) groups outstanding
        if (c + 2 < NC)      cp_wait2();
        else if (c + 1 < NC) cp_wait1();
        else                 cp_wait0();
        __syncthreads();                       // stage c visible; c-1 consumed by all
        if (c + 2 < NC) load_stage(c + 2);     // refill the stage freed at c-1

        const uint32_t sb = sbase + (c % 3) * GEMM_STAGE;

        auto ldfrags = [&](int kk, int buf) {
#pragma unroll
            for (int mi = 0; mi < 2; mi++) {
                uint32_t off = SW128((wm * 32 + mi * 16 + alr) * 128 + kk * 32 + alk * 16);
                ldsm4(ahb[buf][mi], sb + off);
            }
#pragma unroll
            for (int p = 0; p < 2; p++) {
                uint32_t off = SW128((wn * 32 + p * 16 + b4r) * 128 + kk * 32 + b4c * 16);
                ldsm4(bhb[buf][p], sb + 16384 + off);
            }
        };

        ldfrags(0, 0);
#pragma unroll
        for (int kk = 0; kk < 4; kk++) {
            const int buf = kk & 1;
            if (kk < 3) ldfrags(kk + 1, buf ^ 1);
#pragma unroll
            for (int mi = 0; mi < 2; mi++)
#pragma unroll
                for (int ni = 0; ni < 4; ni++)
                    mma16816(acc[mi][ni], ahb[buf][mi], &bhb[buf][ni >> 1][(ni & 1) * 2]);
        }
    }

    const int g   = lane >> 2;
    const int tig = lane & 3;
#pragma unroll
    for (int mi = 0; mi < 2; mi++) {
#pragma unroll
        for (int ni = 0; ni < 4; ni++) {
            int row = m0 + wm * 32 + mi * 16 + g;
            int col = n0 + wn * 32 + ni * 8 + tig * 2;
            float b0 = bias[col], b1 = bias[col + 1];
            float v00 = acc[mi][ni][0] + b0, v01 = acc[mi][ni][1] + b1;
            float v10 = acc[mi][ni][2] + b0, v11 = acc[mi][ni][3] + b1;
            if (mode == 0) {
                *(float2*)(C + (size_t)row * N + col)       = make_float2(v00, v01);
                *(float2*)(C + (size_t)(row + 8) * N + col) = make_float2(v10, v11);
            } else {
                float sc = (col < C_DIM) ? QSCALE : 1.0f;
                *(__half2*)(Ch + (size_t)row * N + col) =
                    __floats2half2_rn(v00 * sc, v01 * sc);
                *(__half2*)(Ch + (size_t)(row + 8) * N + col) =
                    __floats2half2_rn(v10 * sc, v11 * sc);
            }
        }
    }
}

// ---------------------------------------------------------------------------
// Flash attention via fp16 mma.sync, mbarrier pipeline. 128 q x 1 head,
// 8 warps, plain fp16 operands, fp32 accumulators.
// New: at kb == 2qb+1 (diagonal upper block), warps 0-3 are fully causal-
// masked -> skip their S/softmax/PV entirely (exact: p == 0 there).
// ---------------------------------------------------------------------------
#define ATTN_MBAR  (16384 + 2 * 16384)
#define ATTN_SMEM  (ATTN_MBAR + 128)

__global__ __launch_bounds__(256, 2)
void attn_mma(const __half* __restrict__ qkvh, __half* __restrict__ Yh)
{
    extern __shared__ char smem[];
    const uint32_t sb = smem_u32(smem);
    const int qb   = gridDim.x - 1 - blockIdx.x;
    const int h    = blockIdx.y;
    const int tid  = threadIdx.x;
    const int warp = tid >> 5;
    const int lane = tid & 31;
    const int g    = lane >> 2;
    const int quad = lane & 3;
    const int nkb  = 2 * qb + 2;

    const uint32_t full0  = sb + ATTN_MBAR;
    const uint32_t full1  = sb + ATTN_MBAR + 8;
    const uint32_t empty0 = sb + ATTN_MBAR + 16;
    const uint32_t empty1 = sb + ATTN_MBAR + 24;

    if (tid == 0) {
        mbar_init(full0, 256); mbar_init(full1, 256);
        mbar_init(empty0, 256); mbar_init(empty1, 256);
    }
    __syncthreads();

    const int lrv = tid >> 2;
    const int ljv = (tid & 3) * 2;
    auto load_kv = [&](int kb, int s) {
        const uint32_t b = sb + 16384 + s * 16384;
        const size_t kbase = (size_t)(kb * 64 + lrv) * QKV_DIM + C_DIM + h * DHEAD;
        const size_t vbase = kbase + C_DIM;
#pragma unroll
        for (int j = ljv; j < ljv + 2; j++) {
            uint32_t sw = SW128(lrv * 128 + j * 16);
            cp16(b + sw,        qkvh + kbase + j * 8);
            cp16(b + 8192 + sw, qkvh + vbase + j * 8);
        }
    };

    {
        const int lr  = tid >> 1;
        const int lj0 = (tid & 1) * 4;
        const size_t base = (size_t)(qb * 128 + lr) * QKV_DIM + h * DHEAD;
#pragma unroll
        for (int j = lj0; j < lj0 + 4; j++) {
            uint32_t sw = SW128(lr * 128 + j * 16);
            cp16(sb + sw, qkvh + base + j * 8);
        }
    }
    load_kv(0, 0);
    cp_arrive_noinc(full0);
    if (nkb > 1) { load_kv(1, 1); }
    cp_arrive_noinc(full1);

    float oacc[8][4];
#pragma unroll
    for (int i = 0; i < 8; i++)
#pragma unroll
        for (int j = 0; j < 4; j++) oacc[i][j] = 0.f;
    float mr0 = -1e30f, mr1 = -1e30f, lr0 = 0.f, lr1 = 0.f;

    const int alr = lane & 15;
    const int alk = (lane >> 4) & 1;
    const int b4r = ((lane >> 4) & 1) * 8 + (lane & 7);
    const int b4c = (lane >> 3) & 1;
    const int v4r = ((lane >> 3) & 1) * 8 + (lane & 7);
    const int v4c = (lane >> 4) & 1;

    uint32_t fph0 = 0, fph1 = 0, eph0 = 0, eph1 = 0;

    for (int kb = 0; kb < nkb; kb++) {
        const int s = kb & 1;
        const uint32_t kvb = sb + 16384 + s * 16384;

        if (s == 0) { mbar_wait(full0, fph0); fph0 ^= 1; }
        else        { mbar_wait(full1, fph1); fph1 ^= 1; }

        // fully-masked half-CTA skip: rows of warps 0-3 all precede the keys
        const bool active = !(kb == 2 * qb + 1 && warp < 4);

        float sacc[8][4];
        if (active) {
            // ---- S = Q K^T (single product, fp32 acc) ---------------------
#pragma unroll
            for (int i = 0; i < 8; i++)
#pragma unroll
                for (int j = 0; j < 4; j++) sacc[i][j] = 0.f;

#pragma unroll
            for (int kk = 0; kk < 4; kk++) {
                uint32_t aqh[4];
                uint32_t offA = SW128((warp * 16 + alr) * 128 + kk * 32 + alk * 16);
                ldsm4(aqh, sb + offA);
#pragma unroll
                for (int half = 0; half < 2; half++) {
                    uint32_t kh4[2][4];
#pragma unroll
                    for (int p = 0; p < 2; p++) {
                        uint32_t offB = SW128((half * 32 + p * 16 + b4r) * 128 + kk * 32 + b4c * 16);
                        ldsm4(kh4[p], kvb + offB);
                    }
#pragma unroll
                    for (int j = 0; j < 4; j++)
                        mma16816(sacc[half * 4 + j], aqh, &kh4[j >> 1][(j & 1) * 2]);
                }
            }
        }

        // ---- producer duty: refill the OTHER stage for iter kb+1 ----------
        if (kb >= 1 && kb + 1 < nkb) {
            if (s == 0) { mbar_wait(empty1, eph1); eph1 ^= 1;
                          load_kv(kb + 1, 1); cp_arrive_noinc(full1); }
            else        { mbar_wait(empty0, eph0); eph0 ^= 1;
                          load_kv(kb + 1, 0); cp_arrive_noinc(full0); }
        }

        if (active) {
            // ---- causal mask (active only near the diagonal) --------------
            if (kb >= 2 * qb) {
                int r0 = qb * 128 + warp * 16 + g, r1 = r0 + 8;
                int cb = kb * 64;
#pragma unroll
                for (int ni = 0; ni < 8; ni++) {
                    int c = cb + ni * 8 + quad * 2;
                    if (c     > r0) sacc[ni][0] = -1e30f;
                    if (c + 1 > r0) sacc[ni][1] = -1e30f;
                    if (c     > r1) sacc[ni][2] = -1e30f;
                    if (c + 1 > r1) sacc[ni][3] = -1e30f;
                }
            }

            // ---- online softmax (base-2 domain) ---------------------------
            float mx0 = -1e30f, mx1 = -1e30f;
#pragma unroll
            for (int ni = 0; ni < 8; ni++) {
                mx0 = fmaxf(mx0, fmaxf(sacc[ni][0], sacc[ni][1]));
                mx1 = fmaxf(mx1, fmaxf(sacc[ni][2], sacc[ni][3]));
            }
            mx0 = fmaxf(mx0, __shfl_xor_sync(0xffffffffu, mx0, 1));
            mx0 = fmaxf(mx0, __shfl_xor_sync(0xffffffffu, mx0, 2));
            mx1 = fmaxf(mx1, __shfl_xor_sync(0xffffffffu, mx1, 1));
            mx1 = fmaxf(mx1, __shfl_xor_sync(0xffffffffu, mx1, 2));
            float mn0 = fmaxf(mr0, mx0), mn1 = fmaxf(mr1, mx1);
            float c0 = ex2(mr0 - mn0), c1 = ex2(mr1 - mn1);
            mr0 = mn0; mr1 = mn1;

            float rs0 = 0.f, rs1 = 0.f;
#pragma unroll
            for (int ni = 0; ni < 8; ni++) {
                float p0 = ex2(sacc[ni][0] - mn0);
                float p1 = ex2(sacc[ni][1] - mn0);
                float p2 = ex2(sacc[ni][2] - mn1);
                float p3 = ex2(sacc[ni][3] - mn1);
                sacc[ni][0] = p0; sacc[ni][1] = p1; sacc[ni][2] = p2; sacc[ni][3] = p3;
                rs0 += p0 + p1; rs1 += p2 + p3;
            }
            rs0 += __shfl_xor_sync(0xffffffffu, rs0, 1);
            rs0 += __shfl_xor_sync(0xffffffffu, rs0, 2);
            rs1 += __shfl_xor_sync(0xffffffffu, rs1, 1);
            rs1 += __shfl_xor_sync(0xffffffffu, rs1, 2);
            lr0 = lr0 * c0 + rs0;
            lr1 = lr1 * c1 + rs1;
#pragma unroll
            for (int di = 0; di < 8; di++) {
                oacc[di][0] *= c0; oacc[di][1] *= c0;
                oacc[di][2] *= c1; oacc[di][3] *= c1;
            }

            // ---- O += Ph Vh (single product) ------------------------------
#pragma unroll
            for (int ks = 0; ks < 4; ks++) {
                uint32_t aph[4];
                float* s0 = sacc[2 * ks];
                float* s1 = sacc[2 * ks + 1];
                aph[0] = packhf(s0[0], s0[1]);
                aph[1] = packhf(s0[2], s0[3]);
                aph[2] = packhf(s1[0], s1[1]);
                aph[3] = packhf(s1[2], s1[3]);
#pragma unroll
                for (int half = 0; half < 2; half++) {
                    uint32_t vh4[2][4];
#pragma unroll
                    for (int p = 0; p < 2; p++) {
                        int di = half * 4 + p * 2;
                        uint32_t offV = SW128((ks * 16 + v4r) * 128 + (di + v4c) * 16);
                        ldsm4t(vh4[p], kvb + 8192 + offV);
                    }
#pragma unroll
                    for (int j = 0; j < 4; j++)
                        mma16816(oacc[half * 4 + j], aph, &vh4[j >> 1][(j & 1) * 2]);
                }
            }
        }

        if (s == 0) mbar_arrive(empty0);
        else        mbar_arrive(empty1);
    }

    // ---- epilogue: O /= l, write fp16 y -----------------------------------
    float inv0 = 1.f / lr0, inv1 = 1.f / lr1;
    int r0 = qb * 128 + warp * 16 + g;
    size_t b0 = (size_t)r0 * C_DIM + h * DHEAD + quad * 2;
    size_t b1 = b0 + 8 * C_DIM;
#pragma unroll
    for (int di = 0; di < 8; di++) {
        *(__half2*)(Yh + b0 + di * 8) =
            __floats2half2_rn(oacc[di][0] * inv0, oacc[di][1] * inv0);
        *(__half2*)(Yh + b1 + di * 8) =
            __floats2half2_rn(oacc[di][2] * inv1, oacc[di][3] * inv1);
    }
}

// ---------------------------------------------------------------------------
extern "C" void kernel_launch(void* const* d_in, const int* in_sizes, int n_in,
                              void* d_out, int out_size)
{
    const float* x  = (const float*)d_in[0];
    const float* Wq = (const float*)d_in[1];
    const float* bq = (const float*)d_in[2];
    const float* Wk = (const float*)d_in[3];
    const float* bk = (const float*)d_in[4];
    const float* Wv = (const float*)d_in[5];
    const float* bv = (const float*)d_in[6];
    const float* Wp = (const float*)d_in[7];
    const float* bp = (const float*)d_in[8];
    float* out = (float*)d_out;

    __half *xh, *Wh, *Wph, *yh, *qkvh;
    float *bqkv;
    cudaGetSymbolAddress((void**)&xh,    g_xh);
    cudaGetSymbolAddress((void**)&Wh,    g_Wh);
    cudaGetSymbolAddress((void**)&Wph,   g_Wph);
    cudaGetSymbolAddress((void**)&yh,    g_yh);
    cudaGetSymbolAddress((void**)&qkvh,  g_qkvh);
    cudaGetSymbolAddress((void**)&bqkv,  g_bqkv);

    cudaFuncSetAttribute(gemm_f16, cudaFuncAttributeMaxDynamicSharedMemorySize,
                         GEMM_SMEM);
    cudaFuncSetAttribute(attn_mma, cudaFuncAttributeMaxDynamicSharedMemorySize,
                         ATTN_SMEM);

    conv_w4<<<4096, 256>>>((const float4*)Wq, (const float4*)Wk,
                           (const float4*)Wv, (const float4*)Wp,
                           (__half2*)Wh, (__half2*)Wph);
    conv_x<<<4096, 256>>>((const float4*)x, (__half2*)xh, 1048576);
    concat_bias<<<3, 1024>>>(bq, bk, bv, bqkv);

    gemm_f16<<<dim3(QKV_DIM / 64, T_SEQ / 128), 256, GEMM_SMEM>>>(
        xh, Wh, bqkv, nullptr, qkvh, QKV_DIM, C_DIM, 1);

    attn_mma<<<dim3(T_SEQ / 128, NHEAD), 256, ATTN_SMEM>>>(qkvh, yh);

    gemm_f16<<<dim3(C_DIM / 64, T_SEQ / 128), 256, GEMM_SMEM>>>(
        yh, Wph, bp, out, nullptr, C_DIM, C_DIM, 0);
}

// round 16
// speedup vs baseline: 1.0794x; 1.0794x over previous
#include <cuda_runtime.h>
#include <cuda_fp16.h>
#include <cstdint>

#define T_SEQ 4096
#define C_DIM 1024
#define QKV_DIM 3072
#define NHEAD 16
#define DHEAD 64

// ---------------------------------------------------------------------------
// Static device scratch (no allocations allowed)
// ---------------------------------------------------------------------------
__device__ __half g_xh[T_SEQ * C_DIM];            // x fp16
__device__ __half g_Wh[QKV_DIM * C_DIM];          // [Wq;Wk;Wv] fp16
__device__ __half g_Wph[C_DIM * C_DIM];           // Wp fp16
__device__ float  g_bqkv[QKV_DIM];
__device__ __half g_qkvh[T_SEQ * QKV_DIM];        // q | k | v, fp16 (q pre-scaled)
__device__ __half g_yh[T_SEQ * C_DIM];            // y fp16

// q pre-scale: (1/sqrt(64)) * log2(e), so softmax uses ex2 directly
#define QSCALE 0.18033688011112042f

// ---------------------------------------------------------------------------
// PTX helpers (arch-agnostic; no tcgen05 — harness PTX target rejects it)
// ---------------------------------------------------------------------------
__device__ __forceinline__ uint32_t smem_u32(const void* p) {
    uint32_t a;
    asm("{ .reg .u64 t; cvta.to.shared.u64 t, %1; cvt.u32.u64 %0, t; }"
        : "=r"(a) : "l"(p));
    return a;
}
__device__ __forceinline__ void cp16(uint32_t dst, const void* src) {
    asm volatile("cp.async.cg.shared.global [%0], [%1], 16;" :: "r"(dst), "l"(src));
}
__device__ __forceinline__ void cp_commit() {
    asm volatile("cp.async.commit_group;" ::: "memory");
}
__device__ __forceinline__ void cp_wait0() {
    asm volatile("cp.async.wait_group 0;" ::: "memory");
}
__device__ __forceinline__ void cp_wait1() {
    asm volatile("cp.async.wait_group 1;" ::: "memory");
}
__device__ __forceinline__ void ldsm4(uint32_t* r, uint32_t addr) {
    asm volatile("ldmatrix.sync.aligned.m8n8.x4.shared.b16 {%0,%1,%2,%3}, [%4];"
                 : "=r"(r[0]), "=r"(r[1]), "=r"(r[2]), "=r"(r[3]) : "r"(addr));
}
__device__ __forceinline__ void ldsm4t(uint32_t* r, uint32_t addr) {
    asm volatile("ldmatrix.sync.aligned.m8n8.x4.trans.shared.b16 {%0,%1,%2,%3}, [%4];"
                 : "=r"(r[0]), "=r"(r[1]), "=r"(r[2]), "=r"(r[3]) : "r"(addr));
}
// fp16 MMA, fp32 accumulate (rt ~16/SMSP measured)
__device__ __forceinline__ void mma16816(float* c, const uint32_t* a, const uint32_t* b) {
    asm volatile(
        "mma.sync.aligned.m16n8k16.row.col.f32.f16.f16.f32 "
        "{%0,%1,%2,%3}, {%4,%5,%6,%7}, {%8,%9}, {%0,%1,%2,%3};"
        : "+f"(c[0]), "+f"(c[1]), "+f"(c[2]), "+f"(c[3])
        : "r"(a[0]), "r"(a[1]), "r"(a[2]), "r"(a[3]), "r"(b[0]), "r"(b[1]));
}
__device__ __forceinline__ uint32_t packhf(float a, float b) {
    __half2 t = __floats2half2_rn(a, b);
    return *(uint32_t*)&t;
}
__device__ __forceinline__ float ex2(float x) {
    float r;
    asm("ex2.approx.ftz.f32 %0, %1;" : "=f"(r) : "f"(x));
    return r;
}

// ---- mbarrier (sm_80/90 PTX, legal at compute_103) ------------------------
__device__ __forceinline__ void mbar_init(uint32_t a, uint32_t cnt) {
    asm volatile("mbarrier.init.shared.b64 [%0], %1;" :: "r"(a), "r"(cnt) : "memory");
}
__device__ __forceinline__ void mbar_arrive(uint32_t a) {
    asm volatile("{\n\t.reg .b64 t;\n\tmbarrier.arrive.shared.b64 t, [%0];\n\t}"
                 :: "r"(a) : "memory");
}
__device__ __forceinline__ void cp_arrive_noinc(uint32_t a) {
    asm volatile("cp.async.mbarrier.arrive.noinc.shared.b64 [%0];" :: "r"(a) : "memory");
}
__device__ __forceinline__ void mbar_wait(uint32_t a, uint32_t ph) {
    asm volatile(
        "{\n\t.reg .pred P;\n\t"
        "WL%=:\n\t"
        "mbarrier.try_wait.parity.shared.b64 P, [%0], %1;\n\t"
        "@!P bra WL%=;\n\t}"
        :: "r"(a), "r"(ph) : "memory");
}

#define SW128(o) ((o) ^ (((o) >> 3) & 0x70))

// ---------------------------------------------------------------------------
// Fused prologue: convert x + 4 weight matrices to fp16, concat biases.
// Blocks 0..4095: weights (w = b>>10). Blocks 4096..8191: x chunks.
// Blocks 8192..8203: bias concat.
// ---------------------------------------------------------------------------
__global__ void prologue(const float4* __restrict__ x,
                         const float4* __restrict__ Wq, const float4* __restrict__ Wk,
                         const float4* __restrict__ Wv, const float4* __restrict__ Wp,
                         const float* __restrict__ bq, const float* __restrict__ bk,
                         const float* __restrict__ bv,
                         __half2* __restrict__ xh, __half2* __restrict__ Wh,
                         __half2* __restrict__ Wph, float* __restrict__ bqkv)
{
    int b = blockIdx.x;
    if (b < 8192) {
        int w = b >> 10;                                   // 0..7
        int i = (b & 1023) * 256 + threadIdx.x;            // 0..262143
        const float4* src;
        __half2* dst;
        if (w < 4) {
            src = (w == 0) ? Wq : (w == 1) ? Wk : (w == 2) ? Wv : Wp;
            dst = (w == 3) ? Wph : Wh + (size_t)w * 524288;
        } else {
            src = x + (size_t)(w - 4) * 262144;
            dst = xh + (size_t)(w - 4) * 524288;
        }
        float4 v = src[i];
        dst[i * 2]     = __floats2half2_rn(v.x, v.y);
        dst[i * 2 + 1] = __floats2half2_rn(v.z, v.w);
    } else {
        int i = (b - 8192) * 256 + threadIdx.x;            // 0..3071
        if (i < 1024)      bqkv[i] = bq[i];
        else if (i < 2048) bqkv[i] = bk[i - 1024];
        else if (i < 3072) bqkv[i] = bv[i - 2048];
    }
}

// ---------------------------------------------------------------------------
// fp16 single-product GEMM (NT): C = A @ B^T + bias, fp32 acc.
// CTA 128x64, BK=64, 8 warps 4m x 2n, frag double-buffering.
// 3-stage cp.async (72KB smem, 2 CTAs/SM), one __syncthreads per chunk.
// Wait discipline: at iter c only group c+1 is outstanding beyond c
// (c+2 is issued AFTER the wait) -> cp_wait1 guarantees stage c landed.
// mode 0: fp32 C.   mode 1: fp16 Ch, QSCALE applied to cols < C_DIM.
// ---------------------------------------------------------------------------
#define GEMM_STAGE 24576
#define GEMM_SMEM  (3 * GEMM_STAGE)

__global__ __launch_bounds__(256, 2)
void gemm_f16(const __half* __restrict__ A, const __half* __restrict__ B,
              const float* __restrict__ bias, float* __restrict__ C,
              __half* __restrict__ Ch, int N, int K, int mode)
{
    extern __shared__ char smem[];
    const int tid  = threadIdx.x;
    const int warp = tid >> 5;
    const int lane = tid & 31;
    const int wm   = warp >> 1;
    const int wn   = warp & 1;
    const int m0   = blockIdx.y * 128;
    const int n0   = blockIdx.x * 64;
    const uint32_t sbase = smem_u32(smem);
    const int NC = K / 64;   // 16

    const int lrA = tid >> 1;
    const int ljA = (tid & 1) * 4;
    const int lrB = tid >> 2;
    const int ljB = (tid & 3) * 2;

    auto load_stage = [&](int c) {
        const uint32_t sb = sbase + (c % 3) * GEMM_STAGE;
        const size_t ka = (size_t)(m0 + lrA) * K + c * 64;
        const size_t kb = (size_t)(n0 + lrB) * K + c * 64;
#pragma unroll
        for (int j = ljA; j < ljA + 4; j++) {
            uint32_t sw = SW128(lrA * 128 + j * 16);
            cp16(sb + sw, A + ka + j * 8);
        }
#pragma unroll
        for (int j = ljB; j < ljB + 2; j++) {
            uint32_t sw = SW128(lrB * 128 + j * 16);
            cp16(sb + 16384 + sw, B + kb + j * 8);
        }
        cp_commit();
    };

    float acc[2][4][4];
#pragma unroll
    for (int i = 0; i < 2; i++)
#pragma unroll
        for (int j = 0; j < 4; j++)
#pragma unroll
            for (int q = 0; q < 4; q++) acc[i][j][q] = 0.f;

    const int alr = lane & 15;
    const int alk = (lane >> 4) & 1;
    const int b4r = ((lane >> 4) & 1) * 8 + (lane & 7);
    const int b4c = (lane >> 3) & 1;

    uint32_t ahb[2][2][4], bhb[2][2][4];

    load_stage(0);
    load_stage(1);

    for (int c = 0; c < NC; c++) {
        if (c + 1 < NC) cp_wait1();   // stage c done; group c+1 may be in flight
        else            cp_wait0();
        __syncthreads();              // stage c visible to all; stage c-1 consumed
        if (c + 2 < NC) load_stage(c + 2);   // refill the buffer freed at c-1

        const uint32_t sb = sbase + (c % 3) * GEMM_STAGE;

        auto ldfrags = [&](int kk, int buf) {
#pragma unroll
            for (int mi = 0; mi < 2; mi++) {
                uint32_t off = SW128((wm * 32 + mi * 16 + alr) * 128 + kk * 32 + alk * 16);
                ldsm4(ahb[buf][mi], sb + off);
            }
#pragma unroll
            for (int p = 0; p < 2; p++) {
                uint32_t off = SW128((wn * 32 + p * 16 + b4r) * 128 + kk * 32 + b4c * 16);
                ldsm4(bhb[buf][p], sb + 16384 + off);
            }
        };

        ldfrags(0, 0);
#pragma unroll
        for (int kk = 0; kk < 4; kk++) {
            const int buf = kk & 1;
            if (kk < 3) ldfrags(kk + 1, buf ^ 1);
#pragma unroll
            for (int mi = 0; mi < 2; mi++)
#pragma unroll
                for (int ni = 0; ni < 4; ni++)
                    mma16816(acc[mi][ni], ahb[buf][mi], &bhb[buf][ni >> 1][(ni & 1) * 2]);
        }
    }

    const int g   = lane >> 2;
    const int tig = lane & 3;
#pragma unroll
    for (int mi = 0; mi < 2; mi++) {
#pragma unroll
        for (int ni = 0; ni < 4; ni++) {
            int row = m0 + wm * 32 + mi * 16 + g;
            int col = n0 + wn * 32 + ni * 8 + tig * 2;
            float b0 = bias[col], b1 = bias[col + 1];
            float v00 = acc[mi][ni][0] + b0, v01 = acc[mi][ni][1] + b1;
            float v10 = acc[mi][ni][2] + b0, v11 = acc[mi][ni][3] + b1;
            if (mode == 0) {
                *(float2*)(C + (size_t)row * N + col)       = make_float2(v00, v01);
                *(float2*)(C + (size_t)(row + 8) * N + col) = make_float2(v10, v11);
            } else {
                float sc = (col < C_DIM) ? QSCALE : 1.0f;
                *(__half2*)(Ch + (size_t)row * N + col) =
                    __floats2half2_rn(v00 * sc, v01 * sc);
                *(__half2*)(Ch + (size_t)(row + 8) * N + col) =
                    __floats2half2_rn(v10 * sc, v11 * sc);
            }
        }
    }
}

// ---------------------------------------------------------------------------
// Flash attention via fp16 mma.sync, mbarrier pipeline. 128 q x 1 head,
// 8 warps, plain fp16 operands, fp32 accumulators. (Exact R14 WIN body.)
// ---------------------------------------------------------------------------
#define ATTN_MBAR  (16384 + 2 * 16384)
#define ATTN_SMEM  (ATTN_MBAR + 128)

__global__ __launch_bounds__(256, 2)
void attn_mma(const __half* __restrict__ qkvh, __half* __restrict__ Yh)
{
    extern __shared__ char smem[];
    const uint32_t sb = smem_u32(smem);
    const int qb   = gridDim.x - 1 - blockIdx.x;
    const int h    = blockIdx.y;
    const int tid  = threadIdx.x;
    const int warp = tid >> 5;
    const int lane = tid & 31;
    const int g    = lane >> 2;
    const int quad = lane & 3;
    const int nkb  = 2 * qb + 2;

    const uint32_t full0  = sb + ATTN_MBAR;
    const uint32_t full1  = sb + ATTN_MBAR + 8;
    const uint32_t empty0 = sb + ATTN_MBAR + 16;
    const uint32_t empty1 = sb + ATTN_MBAR + 24;

    if (tid == 0) {
        mbar_init(full0, 256); mbar_init(full1, 256);
        mbar_init(empty0, 256); mbar_init(empty1, 256);
    }
    __syncthreads();

    const int lrv = tid >> 2;
    const int ljv = (tid & 3) * 2;
    auto load_kv = [&](int kb, int s) {
        const uint32_t b = sb + 16384 + s * 16384;
        const size_t kbase = (size_t)(kb * 64 + lrv) * QKV_DIM + C_DIM + h * DHEAD;
        const size_t vbase = kbase + C_DIM;
#pragma unroll
        for (int j = ljv; j < ljv + 2; j++) {
            uint32_t sw = SW128(lrv * 128 + j * 16);
            cp16(b + sw,        qkvh + kbase + j * 8);
            cp16(b + 8192 + sw, qkvh + vbase + j * 8);
        }
    };

    {
        const int lr  = tid >> 1;
        const int lj0 = (tid & 1) * 4;
        const size_t base = (size_t)(qb * 128 + lr) * QKV_DIM + h * DHEAD;
#pragma unroll
        for (int j = lj0; j < lj0 + 4; j++) {
            uint32_t sw = SW128(lr * 128 + j * 16);
            cp16(sb + sw, qkvh + base + j * 8);
        }
    }
    load_kv(0, 0);
    cp_arrive_noinc(full0);
    if (nkb > 1) { load_kv(1, 1); }
    cp_arrive_noinc(full1);

    float oacc[8][4];
#pragma unroll
    for (int i = 0; i < 8; i++)
#pragma unroll
        for (int j = 0; j < 4; j++) oacc[i][j] = 0.f;
    float mr0 = -1e30f, mr1 = -1e30f, lr0 = 0.f, lr1 = 0.f;

    const int alr = lane & 15;
    const int alk = (lane >> 4) & 1;
    const int b4r = ((lane >> 4) & 1) * 8 + (lane & 7);
    const int b4c = (lane >> 3) & 1;
    const int v4r = ((lane >> 3) & 1) * 8 + (lane & 7);
    const int v4c = (lane >> 4) & 1;

    uint32_t fph0 = 0, fph1 = 0, eph0 = 0, eph1 = 0;

    for (int kb = 0; kb < nkb; kb++) {
        const int s = kb & 1;
        const uint32_t kvb = sb + 16384 + s * 16384;

        if (s == 0) { mbar_wait(full0, fph0); fph0 ^= 1; }
        else        { mbar_wait(full1, fph1); fph1 ^= 1; }

        // ---- S = Q K^T (single product, fp32 acc) -------------------------
        float sacc[8][4];
#pragma unroll
        for (int i = 0; i < 8; i++)
#pragma unroll
            for (int j = 0; j < 4; j++) sacc[i][j] = 0.f;

#pragma unroll
        for (int kk = 0; kk < 4; kk++) {
            uint32_t aqh[4];
            uint32_t offA = SW128((warp * 16 + alr) * 128 + kk * 32 + alk * 16);
            ldsm4(aqh, sb + offA);
#pragma unroll
            for (int half = 0; half < 2; half++) {
                uint32_t kh4[2][4];
#pragma unroll
                for (int p = 0; p < 2; p++) {
                    uint32_t offB = SW128((half * 32 + p * 16 + b4r) * 128 + kk * 32 + b4c * 16);
                    ldsm4(kh4[p], kvb + offB);
                }
#pragma unroll
                for (int j = 0; j < 4; j++)
                    mma16816(sacc[half * 4 + j], aqh, &kh4[j >> 1][(j & 1) * 2]);
            }
        }

        // ---- producer duty: refill the OTHER stage for iter kb+1 ----------
        if (kb >= 1 && kb + 1 < nkb) {
            if (s == 0) { mbar_wait(empty1, eph1); eph1 ^= 1;
                          load_kv(kb + 1, 1); cp_arrive_noinc(full1); }
            else        { mbar_wait(empty0, eph0); eph0 ^= 1;
                          load_kv(kb + 1, 0); cp_arrive_noinc(full0); }
        }

        // ---- causal mask (active only near the diagonal) ------------------
        if (kb >= 2 * qb) {
            int r0 = qb * 128 + warp * 16 + g, r1 = r0 + 8;
            int cb = kb * 64;
#pragma unroll
            for (int ni = 0; ni < 8; ni++) {
                int c = cb + ni * 8 + quad * 2;
                if (c     > r0) sacc[ni][0] = -1e30f;
                if (c + 1 > r0) sacc[ni][1] = -1e30f;
                if (c     > r1) sacc[ni][2] = -1e30f;
                if (c + 1 > r1) sacc[ni][3] = -1e30f;
            }
        }

        // ---- online softmax (base-2 domain) -------------------------------
        float mx0 = -1e30f, mx1 = -1e30f;
#pragma unroll
        for (int ni = 0; ni < 8; ni++) {
            mx0 = fmaxf(mx0, fmaxf(sacc[ni][0], sacc[ni][1]));
            mx1 = fmaxf(mx1, fmaxf(sacc[ni][2], sacc[ni][3]));
        }
        mx0 = fmaxf(mx0, __shfl_xor_sync(0xffffffffu, mx0, 1));
        mx0 = fmaxf(mx0, __shfl_xor_sync(0xffffffffu, mx0, 2));
        mx1 = fmaxf(mx1, __shfl_xor_sync(0xffffffffu, mx1, 1));
        mx1 = fmaxf(mx1, __shfl_xor_sync(0xffffffffu, mx1, 2));
        float mn0 = fmaxf(mr0, mx0), mn1 = fmaxf(mr1, mx1);
        float c0 = ex2(mr0 - mn0), c1 = ex2(mr1 - mn1);
        mr0 = mn0; mr1 = mn1;

        float rs0 = 0.f, rs1 = 0.f;
#pragma unroll
        for (int ni = 0; ni < 8; ni++) {
            float p0 = ex2(sacc[ni][0] - mn0);
            float p1 = ex2(sacc[ni][1] - mn0);
            float p2 = ex2(sacc[ni][2] - mn1);
            float p3 = ex2(sacc[ni][3] - mn1);
            sacc[ni][0] = p0; sacc[ni][1] = p1; sacc[ni][2] = p2; sacc[ni][3] = p3;
            rs0 += p0 + p1; rs1 += p2 + p3;
        }
        rs0 += __shfl_xor_sync(0xffffffffu, rs0, 1);
        rs0 += __shfl_xor_sync(0xffffffffu, rs0, 2);
        rs1 += __shfl_xor_sync(0xffffffffu, rs1, 1);
        rs1 += __shfl_xor_sync(0xffffffffu, rs1, 2);
        lr0 = lr0 * c0 + rs0;
        lr1 = lr1 * c1 + rs1;
#pragma unroll
        for (int di = 0; di < 8; di++) {
            oacc[di][0] *= c0; oacc[di][1] *= c0;
            oacc[di][2] *= c1; oacc[di][3] *= c1;
        }

        // ---- O += Ph Vh (single product) ----------------------------------
#pragma unroll
        for (int ks = 0; ks < 4; ks++) {
            uint32_t aph[4];
            float* s0 = sacc[2 * ks];
            float* s1 = sacc[2 * ks + 1];
            aph[0] = packhf(s0[0], s0[1]);
            aph[1] = packhf(s0[2], s0[3]);
            aph[2] = packhf(s1[0], s1[1]);
            aph[3] = packhf(s1[2], s1[3]);
#pragma unroll
            for (int half = 0; half < 2; half++) {
                uint32_t vh4[2][4];
#pragma unroll
                for (int p = 0; p < 2; p++) {
                    int di = half * 4 + p * 2;
                    uint32_t offV = SW128((ks * 16 + v4r) * 128 + (di + v4c) * 16);
                    ldsm4t(vh4[p], kvb + 8192 + offV);
                }
#pragma unroll
                for (int j = 0; j < 4; j++)
                    mma16816(oacc[half * 4 + j], aph, &vh4[j >> 1][(j & 1) * 2]);
            }
        }

        if (s == 0) mbar_arrive(empty0);
        else        mbar_arrive(empty1);
    }

    // ---- epilogue: O /= l, write fp16 y -----------------------------------
    float inv0 = 1.f / lr0, inv1 = 1.f / lr1;
    int r0 = qb * 128 + warp * 16 + g;
    size_t b0 = (size_t)r0 * C_DIM + h * DHEAD + quad * 2;
    size_t b1 = b0 + 8 * C_DIM;
#pragma unroll
    for (int di = 0; di < 8; di++) {
        *(__half2*)(Yh + b0 + di * 8) =
            __floats2half2_rn(oacc[di][0] * inv0, oacc[di][1] * inv0);
        *(__half2*)(Yh + b1 + di * 8) =
            __floats2half2_rn(oacc[di][2] * inv1, oacc[di][3] * inv1);
    }
}

// ---------------------------------------------------------------------------
extern "C" void kernel_launch(void* const* d_in, const int* in_sizes, int n_in,
                              void* d_out, int out_size)
{
    const float* x  = (const float*)d_in[0];
    const float* Wq = (const float*)d_in[1];
    const float* bq = (const float*)d_in[2];
    const float* Wk = (const float*)d_in[3];
    const float* bk = (const float*)d_in[4];
    const float* Wv = (const float*)d_in[5];
    const float* bv = (const float*)d_in[6];
    const float* Wp = (const float*)d_in[7];
    const float* bp = (const float*)d_in[8];
    float* out = (float*)d_out;

    __half *xh, *Wh, *Wph, *yh, *qkvh;
    float *bqkv;
    cudaGetSymbolAddress((void**)&xh,    g_xh);
    cudaGetSymbolAddress((void**)&Wh,    g_Wh);
    cudaGetSymbolAddress((void**)&Wph,   g_Wph);
    cudaGetSymbolAddress((void**)&yh,    g_yh);
    cudaGetSymbolAddress((void**)&qkvh,  g_qkvh);
    cudaGetSymbolAddress((void**)&bqkv,  g_bqkv);

    cudaFuncSetAttribute(gemm_f16, cudaFuncAttributeMaxDynamicSharedMemorySize,
                         GEMM_SMEM);
    cudaFuncSetAttribute(attn_mma, cudaFuncAttributeMaxDynamicSharedMemorySize,
                         ATTN_SMEM);

    // 1: fused prologue (x + 4 weights to fp16, bias concat)
    prologue<<<8204, 256>>>((const float4*)x,
                            (const float4*)Wq, (const float4*)Wk,
                            (const float4*)Wv, (const float4*)Wp,
                            bq, bk, bv,
                            (__half2*)xh, (__half2*)Wh, (__half2*)Wph, bqkv);

    // 2: fused QKV projection -> fp16 q|k|v (q pre-scaled)
    gemm_f16<<<dim3(QKV_DIM / 64, T_SEQ / 128), 256, GEMM_SMEM>>>(
        xh, Wh, bqkv, nullptr, qkvh, QKV_DIM, C_DIM, 1);

    // 3: attention -> fp16 y
    attn_mma<<<dim3(T_SEQ / 128, NHEAD), 256, ATTN_SMEM>>>(qkvh, yh);

    // 4: output projection -> fp32 out
    gemm_f16<<<dim3(C_DIM / 64, T_SEQ / 128), 256, GEMM_SMEM>>>(
        yh, Wph, bp, out, nullptr, C_DIM, C_DIM, 0);
}